// round 8
// baseline (speedup 1.0000x reference)
#include <cuda_runtime.h>

// GraphProposalNetwork, fp32 + packed f32x2, block-cooperative.
//  - feat layer fused into u/v:  u[n] = in[n]@Wpu + bu,  v[n] = in[n]@Wpv + bv
//    where Wpu = Wp@W1[:16], Wpv = Wp@W1[16:], bu = bp@W1[:16]+b1, bv = bp@W1[16:]
//  - pair(i,j) layer-1 preact = u[i] + v[j]  (b1 folded into u)
//  - layer 2 in packed fma.rn.f32x2 with W2 restaged interleaved/transposed
//  - lrelu(x) = 0.6x + 0.4|x|  (exact for slope 0.2, branch-free, packable)

#define NN      10
#define NB      12            // batches per block
#define THREADS 256
#define UST     34            // u/v row stride (floats): 136B rows, 8B aligned,
                              // banks (2i+2q)%32 -> conflict-free for 10 rows

typedef unsigned long long ull;

__device__ __forceinline__ ull f2_add(ull a, ull b) {
    ull d; asm("add.rn.f32x2 %0, %1, %2;" : "=l"(d) : "l"(a), "l"(b)); return d;
}
__device__ __forceinline__ ull f2_mul(ull a, ull b) {
    ull d; asm("mul.rn.f32x2 %0, %1, %2;" : "=l"(d) : "l"(a), "l"(b)); return d;
}
__device__ __forceinline__ ull f2_fma(ull a, ull b, ull c) {
    ull d; asm("fma.rn.f32x2 %0, %1, %2, %3;" : "=l"(d) : "l"(a), "l"(b), "l"(c)); return d;
}
__device__ __forceinline__ float2 unpack2(ull x) {
    float lo, hi;
    asm("mov.b64 {%0, %1}, %2;" : "=f"(lo), "=f"(hi) : "l"(x));
    return make_float2(lo, hi);
}

// packed constants: dup(0.6f), dup(0.4f)
#define C06 0x3F19999A3F19999Aull
#define C04 0x3ECCCCCD3ECCCCCDull
#define ABSM 0x7FFFFFFF7FFFFFFFull

__device__ __forceinline__ ull lrelu2(ull x) {
    // 0.6*x + 0.4*|x|  ==  leaky_relu(x, 0.2)
    return f2_fma(x & ABSM, C04, f2_mul(x, C06));
}
__device__ __forceinline__ float lrelu1(float x) {
    return fmaxf(x, 0.2f * x);
}

__global__ __launch_bounds__(THREADS, 2)
void gpn_kernel(const float* __restrict__ pos,   // [B,10,2]
                const float* __restrict__ ori,   // [B,10,1]
                const float* __restrict__ Wp,    // [3,16]
                const float* __restrict__ bp,    // [16]
                const float* __restrict__ W1,    // [32,32]
                const float* __restrict__ b1,    // [32]
                const float* __restrict__ W2,    // [32,8]
                const float* __restrict__ b2,    // [8]
                const float* __restrict__ W3,    // [8,2]
                const float* __restrict__ b3,    // [2]
                float* __restrict__ out_edge,    // [B,10,10,2]
                float* __restrict__ out_adj,     // [B,10,10] (float), may be null
                int B)
{
    __shared__ float sWpu[3][32], sWpv[3][32];
    __shared__ float sbu[32], sbv[32];
    __shared__ __align__(16) float2 sW2t[8][16];  // [m][k] = (W2[2k][m], W2[2k+1][m])
    __shared__ float sW3[16], sb2[8], sb3[2];
    __shared__ float sIn[NB][NN][3];
    __shared__ __align__(16) float sU[NB][NN * UST];
    __shared__ __align__(16) float sV[NB][NN * UST];

    const int tid = threadIdx.x;

    // ---- stage fused weights (block-cooperative, reads global directly) ----
    {
        int t = tid;
        if (t < 96) {                      // Wpu[d][c] = sum_k Wp[d][k] * W1[k][c]
            int d = t >> 5, c = t & 31;
            float a = 0.f;
            #pragma unroll
            for (int k = 0; k < 16; ++k) a += Wp[d * 16 + k] * W1[k * 32 + c];
            sWpu[d][c] = a;
        } else if (t < 192) {              // Wpv[d][c] = sum_k Wp[d][k] * W1[16+k][c]
            int tt = t - 96, d = tt >> 5, c = tt & 31;
            float a = 0.f;
            #pragma unroll
            for (int k = 0; k < 16; ++k) a += Wp[d * 16 + k] * W1[(16 + k) * 32 + c];
            sWpv[d][c] = a;
        } else if (t < 224) {              // bu[c] = b1[c] + sum_k bp[k] * W1[k][c]
            int c = t - 192;
            float a = b1[c];
            #pragma unroll
            for (int k = 0; k < 16; ++k) a += bp[k] * W1[k * 32 + c];
            sbu[c] = a;
        } else {                           // bv[c] = sum_k bp[k] * W1[16+k][c]
            int c = t - 224;
            float a = 0.f;
            #pragma unroll
            for (int k = 0; k < 16; ++k) a += bp[k] * W1[(16 + k) * 32 + c];
            sbv[c] = a;
        }
    }
    if (tid < 128) {                       // W2 transposed+interleaved
        int m = tid >> 4, k = tid & 15;
        sW2t[m][k] = make_float2(W2[(2 * k) * 8 + m], W2[(2 * k + 1) * 8 + m]);
    }
    if (tid < 16) sW3[tid] = W3[tid];
    if (tid < 8)  sb2[tid] = b2[tid];
    if (tid < 2)  sb3[tid] = b3[tid];

    // ---- stage inputs for NB batches ----
    {
        int s = tid;                       // NB*20 = 240 < 256
        if (s < NB * 20) {
            int bl = s / 20, r = s - bl * 20;
            int bb = blockIdx.x * NB + bl;
            if (bb < B) sIn[bl][r >> 1][r & 1] = pos[(size_t)bb * 20 + r];
        }
    }
    {
        int s = tid;                       // NB*10 = 120 < 256
        if (s < NB * 10) {
            int bl = s / 10, n = s - bl * 10;
            int bb = blockIdx.x * NB + bl;
            if (bb < B) sIn[bl][n][2] = ori[(size_t)bb * 10 + n];
        }
    }
    __syncthreads();

    // ---- u/v projections: NB*10*32 = 3840 outputs, 15 per thread ----
    #pragma unroll
    for (int q = 0; q < (NB * NN * 32) / THREADS; ++q) {
        int s = tid + q * THREADS;
        int c = s & 31;
        int rest = s >> 5;
        int bl = rest / 10, n = rest - bl * 10;
        float x0 = sIn[bl][n][0], x1 = sIn[bl][n][1], x2 = sIn[bl][n][2];
        float u = sbu[c] + x0 * sWpu[0][c] + x1 * sWpu[1][c] + x2 * sWpu[2][c];
        float v = sbv[c] + x0 * sWpv[0][c] + x1 * sWpv[1][c] + x2 * sWpv[2][c];
        sU[bl][n * UST + c] = u;
        sV[bl][n * UST + c] = v;
    }
    __syncthreads();

    // ---- pair phase: NB*100 = 1200 pairs over 5 rounds of 256 ----
    #pragma unroll 1
    for (int r = 0; r < (NB * 100 + THREADS - 1) / THREADS; ++r) {
        int t = tid + r * THREADS;
        if (t >= NB * 100) break;
        int bl = t / 100;
        int p  = t - bl * 100;
        int bb = blockIdx.x * NB + bl;
        if (bb >= B) continue;

        int i  = p / 10;
        int jj = p - i * 10;
        // idx[i,0] = i ; idx[i,1:] = all j != i ascending
        int j = (jj == 0) ? i : ((jj <= i) ? jj - 1 : jj);

        // h1 = lrelu(u[i] + v[j]) as 16 packed f32x2 (channels 2k, 2k+1)
        const ull* up = (const ull*)&sU[bl][i * UST];
        const ull* vp = (const ull*)&sV[bl][j * UST];
        ull h[16];
        #pragma unroll
        for (int q = 0; q < 16; ++q)
            h[q] = lrelu2(f2_add(up[q], vp[q]));

        // layer 2: acc2[m] = (even-channel partial, odd-channel partial)
        ull acc2[8];
        #pragma unroll
        for (int m = 0; m < 8; ++m) acc2[m] = 0ull;
        #pragma unroll
        for (int m = 0; m < 8; ++m) {
            const ulonglong2* wp2 = (const ulonglong2*)&sW2t[m][0];
            #pragma unroll
            for (int e = 0; e < 8; ++e) {
                ulonglong2 wv = wp2[e];
                acc2[m] = f2_fma(h[2 * e],     wv.x, acc2[m]);
                acc2[m] = f2_fma(h[2 * e + 1], wv.y, acc2[m]);
            }
        }

        // layer 3 + argmax
        float e0 = sb3[0], e1 = sb3[1];
        #pragma unroll
        for (int m = 0; m < 8; ++m) {
            float2 f = unpack2(acc2[m]);
            float a  = f.x + f.y + sb2[m];
            float h2 = lrelu1(a);
            e0 += h2 * sW3[2 * m];
            e1 += h2 * sW3[2 * m + 1];
        }

        ((float2*)out_edge)[(size_t)bb * 100 + p] = make_float2(e0, e1);
        if (out_adj) out_adj[(size_t)bb * 100 + p] = (e1 > e0) ? 1.0f : 0.0f;
    }
}

extern "C" void kernel_launch(void* const* d_in, const int* in_sizes, int n_in,
                              void* d_out, int out_size)
{
    const float* pos = (const float*)d_in[0];
    const float* ori = (const float*)d_in[1];
    const float* Wp  = (const float*)d_in[2];
    const float* bp  = (const float*)d_in[3];
    const float* W1  = (const float*)d_in[4];
    const float* b1  = (const float*)d_in[5];
    const float* W2  = (const float*)d_in[6];
    const float* b2  = (const float*)d_in[7];
    const float* W3  = (const float*)d_in[8];
    const float* b3  = (const float*)d_in[9];

    const int B = in_sizes[0] / 20;   // position is [B,10,2]

    float* out      = (float*)d_out;
    float* out_edge = out;            // B*100*2 floats
    float* out_adj  = ((size_t)out_size >= (size_t)B * 300)
                        ? out + (size_t)B * 200 : (float*)0;

    const int blocks = (B + NB - 1) / NB;
    gpn_kernel<<<blocks, THREADS>>>(pos, ori, Wp, bp, W1, b1, W2, b2, W3, b3,
                                    out_edge, out_adj, B);
}

// round 9
// speedup vs baseline: 1.7205x; 1.7205x over previous
#include <cuda_runtime.h>

// GraphProposalNetwork, scalar fp32, block-cooperative (12 batches/block).
//  - feat layer fused into u/v:  u[n] = in[n]@Wpu + bu,  v[n] = in[n]@Wpv + bv
//    (Wpu = Wp@W1[:16], Wpv = Wp@W1[16:], bu = bp@W1[:16]+b1, bv = bp@W1[16:])
//  - pair(i,j) layer-1 preact = u[i] + v[j]
//  - scalar FFMA pair body (known-good R4 structure), rounds NOT unrolled to
//    keep regs <= 128 -> 2 blocks/SM (2x occupancy vs R4's 255-reg version)

#define NN      10
#define NB      12
#define THREADS 256
#define UST     36   // u/v row stride (floats): 144B, 16B-aligned for LDS.128

__device__ __forceinline__ float lrelu1(float x) {
    return fmaxf(x, 0.2f * x);   // exact for slope 0.2 < 1
}

__global__ __launch_bounds__(THREADS, 2)
void gpn_kernel(const float* __restrict__ pos,   // [B,10,2]
                const float* __restrict__ ori,   // [B,10,1]
                const float* __restrict__ Wp,    // [3,16]
                const float* __restrict__ bp,    // [16]
                const float* __restrict__ W1,    // [32,32]
                const float* __restrict__ b1,    // [32]
                const float* __restrict__ W2,    // [32,8]
                const float* __restrict__ b2,    // [8]
                const float* __restrict__ W3,    // [8,2]
                const float* __restrict__ b3,    // [2]
                float* __restrict__ out_edge,    // [B,10,10,2]
                float* __restrict__ out_adj,     // [B,10,10] (float), may be null
                int B)
{
    __shared__ float sWpu[3][32], sWpv[3][32];
    __shared__ float sbu[32], sbv[32];
    __shared__ __align__(16) float sW2[32 * 8];
    __shared__ float sW3[16], sb2[8], sb3[2];
    __shared__ float sIn[NB][NN][3];
    __shared__ __align__(16) float sU[NB][NN * UST];
    __shared__ __align__(16) float sV[NB][NN * UST];

    const int tid = threadIdx.x;

    // ---- stage fused weights (block-cooperative) ----
    {
        int t = tid;
        if (t < 96) {                       // Wpu[d][c] = sum_k Wp[d][k]*W1[k][c]
            int d = t >> 5, c = t & 31;
            float a = 0.f;
            #pragma unroll
            for (int k = 0; k < 16; ++k) a += Wp[d * 16 + k] * W1[k * 32 + c];
            sWpu[d][c] = a;
        } else if (t < 192) {               // Wpv[d][c] = sum_k Wp[d][k]*W1[16+k][c]
            int tt = t - 96, d = tt >> 5, c = tt & 31;
            float a = 0.f;
            #pragma unroll
            for (int k = 0; k < 16; ++k) a += Wp[d * 16 + k] * W1[(16 + k) * 32 + c];
            sWpv[d][c] = a;
        } else if (t < 224) {               // bu[c] = b1[c] + sum_k bp[k]*W1[k][c]
            int c = t - 192;
            float a = b1[c];
            #pragma unroll
            for (int k = 0; k < 16; ++k) a += bp[k] * W1[k * 32 + c];
            sbu[c] = a;
        } else {                            // bv[c] = sum_k bp[k]*W1[16+k][c]
            int c = t - 224;
            float a = 0.f;
            #pragma unroll
            for (int k = 0; k < 16; ++k) a += bp[k] * W1[(16 + k) * 32 + c];
            sbv[c] = a;
        }
    }
    if (tid < 256) { int t = tid; if (t < 32 * 8) sW2[t] = W2[t]; }
    if (tid < 16) sW3[tid] = W3[tid];
    if (tid < 8)  sb2[tid] = b2[tid];
    if (tid < 2)  sb3[tid] = b3[tid];

    // ---- stage inputs for NB batches ----
    if (tid < NB * 20) {                    // 240 threads
        int bl = tid / 20, r = tid - bl * 20;
        int bb = blockIdx.x * NB + bl;
        if (bb < B) sIn[bl][r >> 1][r & 1] = pos[(size_t)bb * 20 + r];
    }
    if (tid < NB * 10) {                    // 120 threads
        int bl = tid / 10, n = tid - bl * 10;
        int bb = blockIdx.x * NB + bl;
        if (bb < B) sIn[bl][n][2] = ori[(size_t)bb * 10 + n];
    }
    __syncthreads();

    // ---- u/v projections: NB*10*32 = 3840 outputs, 15 per thread ----
    #pragma unroll
    for (int q = 0; q < (NB * NN * 32) / THREADS; ++q) {
        int s = tid + q * THREADS;
        int c = s & 31;
        int rest = s >> 5;
        int bl = rest / 10, n = rest - bl * 10;
        float x0 = sIn[bl][n][0], x1 = sIn[bl][n][1], x2 = sIn[bl][n][2];
        float u = sbu[c] + x0 * sWpu[0][c] + x1 * sWpu[1][c] + x2 * sWpu[2][c];
        float v = sbv[c] + x0 * sWpv[0][c] + x1 * sWpv[1][c] + x2 * sWpv[2][c];
        sU[bl][n * UST + c] = u;
        sV[bl][n * UST + c] = v;
    }
    __syncthreads();

    // ---- per-thread register copies of tiny tail weights (24 regs) ----
    float b2r[8], w30[8], w31[8];
    #pragma unroll
    for (int m = 0; m < 8; ++m) {
        b2r[m] = sb2[m];
        w30[m] = sW3[2 * m];
        w31[m] = sW3[2 * m + 1];
    }
    const float b30 = sb3[0], b31 = sb3[1];
    const float4* w2v = (const float4*)sW2;

    // ---- pair phase: NB*100 = 1200 pairs over 5 rounds (NOT unrolled) ----
    #pragma unroll 1
    for (int r = 0; r < (NB * 100 + THREADS - 1) / THREADS; ++r) {
        int t = tid + r * THREADS;
        if (t >= NB * 100) break;
        int bl = t / 100;
        int p  = t - bl * 100;
        int bb = blockIdx.x * NB + bl;
        if (bb >= B) continue;

        int i  = p / 10;
        int jj = p - i * 10;
        // idx[i,0] = i ; idx[i,1:] = all j != i ascending
        int j = (jj == 0) ? i : ((jj <= i) ? jj - 1 : jj);

        // h1 = lrelu(u[i] + v[j])
        float h1[32];
        const float4* uv = (const float4*)&sU[bl][i * UST];
        const float4* vv = (const float4*)&sV[bl][j * UST];
        #pragma unroll
        for (int q = 0; q < 8; ++q) {
            float4 ua = uv[q];
            float4 va = vv[q];
            h1[4 * q + 0] = lrelu1(ua.x + va.x);
            h1[4 * q + 1] = lrelu1(ua.y + va.y);
            h1[4 * q + 2] = lrelu1(ua.z + va.z);
            h1[4 * q + 3] = lrelu1(ua.w + va.w);
        }

        // layer 2: acc = h1 @ W2 + b2  (8 independent FMA chains)
        float acc[8];
        #pragma unroll
        for (int m = 0; m < 8; ++m) acc[m] = b2r[m];
        #pragma unroll
        for (int c = 0; c < 32; ++c) {
            float4 wa = w2v[2 * c];
            float4 wb = w2v[2 * c + 1];
            float  hc = h1[c];
            acc[0] += hc * wa.x; acc[1] += hc * wa.y;
            acc[2] += hc * wa.z; acc[3] += hc * wa.w;
            acc[4] += hc * wb.x; acc[5] += hc * wb.y;
            acc[6] += hc * wb.z; acc[7] += hc * wb.w;
        }

        // layer 3 + argmax
        float e0 = b30, e1 = b31;
        #pragma unroll
        for (int m = 0; m < 8; ++m) {
            float h2 = lrelu1(acc[m]);
            e0 += h2 * w30[m];
            e1 += h2 * w31[m];
        }

        ((float2*)out_edge)[(size_t)bb * 100 + p] = make_float2(e0, e1);
        if (out_adj) out_adj[(size_t)bb * 100 + p] = (e1 > e0) ? 1.0f : 0.0f;
    }
}

extern "C" void kernel_launch(void* const* d_in, const int* in_sizes, int n_in,
                              void* d_out, int out_size)
{
    const float* pos = (const float*)d_in[0];
    const float* ori = (const float*)d_in[1];
    const float* Wp  = (const float*)d_in[2];
    const float* bp  = (const float*)d_in[3];
    const float* W1  = (const float*)d_in[4];
    const float* b1  = (const float*)d_in[5];
    const float* W2  = (const float*)d_in[6];
    const float* b2  = (const float*)d_in[7];
    const float* W3  = (const float*)d_in[8];
    const float* b3  = (const float*)d_in[9];

    const int B = in_sizes[0] / 20;   // position is [B,10,2]

    float* out      = (float*)d_out;
    float* out_edge = out;            // B*100*2 floats
    float* out_adj  = ((size_t)out_size >= (size_t)B * 300)
                        ? out + (size_t)B * 200 : (float*)0;

    const int blocks = (B + NB - 1) / NB;
    gpn_kernel<<<blocks, THREADS>>>(pos, ori, Wp, bp, W1, b1, W2, b2, W3, b3,
                                    out_edge, out_adj, B);
}

// round 13
// speedup vs baseline: 2.2466x; 1.3058x over previous
#include <cuda_runtime.h>

// GraphProposalNetwork, scalar fp32, block-cooperative (12 batches/block),
// TWO pairs per thread per round.
//  - feat layer fused into u/v (Wpu=Wp@W1[:16], Wpv=Wp@W1[16:], biases folded)
//  - pair(i,j) layer-1 preact = u[i] + v[j]
//  - duo (p, p+1) with p even shares batch AND i: u[i] and all of W2 are
//    loaded from shared once per duo -> ~45% fewer LDS, 16 FMA chains of ILP.

#define NN      10
#define NB      12
#define THREADS 256
#define UST     36   // u/v row stride (floats): 144B, 16B-aligned for LDS.128
#define NDUO    ((NB * 100) / 2)   // 600 duos per block

__device__ __forceinline__ float lrelu1(float x) {
    return fmaxf(x, 0.2f * x);   // exact for slope 0.2 < 1
}

__global__ __launch_bounds__(THREADS, 2)
void gpn_kernel(const float* __restrict__ pos,   // [B,10,2]
                const float* __restrict__ ori,   // [B,10,1]
                const float* __restrict__ Wp,    // [3,16]
                const float* __restrict__ bp,    // [16]
                const float* __restrict__ W1,    // [32,32]
                const float* __restrict__ b1,    // [32]
                const float* __restrict__ W2,    // [32,8]
                const float* __restrict__ b2,    // [8]
                const float* __restrict__ W3,    // [8,2]
                const float* __restrict__ b3,    // [2]
                float* __restrict__ out_edge,    // [B,10,10,2]
                float* __restrict__ out_adj,     // [B,10,10] (float), may be null
                int B)
{
    __shared__ float sWpu[3][32], sWpv[3][32];
    __shared__ float sbu[32], sbv[32];
    __shared__ __align__(16) float sW2[32 * 8];
    __shared__ float sW3[16], sb2[8], sb3[2];
    __shared__ float sIn[NB][NN][3];
    __shared__ __align__(16) float sU[NB][NN * UST];
    __shared__ __align__(16) float sV[NB][NN * UST];

    const int tid = threadIdx.x;

    // ---- stage fused weights (block-cooperative) ----
    {
        int t = tid;
        if (t < 96) {                       // Wpu[d][c] = sum_k Wp[d][k]*W1[k][c]
            int d = t >> 5, c = t & 31;
            float a = 0.f;
            #pragma unroll
            for (int k = 0; k < 16; ++k) a += Wp[d * 16 + k] * W1[k * 32 + c];
            sWpu[d][c] = a;
        } else if (t < 192) {               // Wpv[d][c] = sum_k Wp[d][k]*W1[16+k][c]
            int tt = t - 96, d = tt >> 5, c = tt & 31;
            float a = 0.f;
            #pragma unroll
            for (int k = 0; k < 16; ++k) a += Wp[d * 16 + k] * W1[(16 + k) * 32 + c];
            sWpv[d][c] = a;
        } else if (t < 224) {               // bu[c] = b1[c] + sum_k bp[k]*W1[k][c]
            int c = t - 192;
            float a = b1[c];
            #pragma unroll
            for (int k = 0; k < 16; ++k) a += bp[k] * W1[k * 32 + c];
            sbu[c] = a;
        } else {                            // bv[c] = sum_k bp[k]*W1[16+k][c]
            int c = t - 224;
            float a = 0.f;
            #pragma unroll
            for (int k = 0; k < 16; ++k) a += bp[k] * W1[(16 + k) * 32 + c];
            sbv[c] = a;
        }
    }
    if (tid < 32 * 8) sW2[tid] = W2[tid];
    if (tid < 16) sW3[tid] = W3[tid];
    if (tid < 8)  sb2[tid] = b2[tid];
    if (tid < 2)  sb3[tid] = b3[tid];

    // ---- stage inputs for NB batches ----
    if (tid < NB * 20) {                    // 240 threads
        int bl = tid / 20, r = tid - bl * 20;
        int bb = blockIdx.x * NB + bl;
        if (bb < B) sIn[bl][r >> 1][r & 1] = pos[(size_t)bb * 20 + r];
    }
    if (tid < NB * 10) {                    // 120 threads
        int bl = tid / 10, n = tid - bl * 10;
        int bb = blockIdx.x * NB + bl;
        if (bb < B) sIn[bl][n][2] = ori[(size_t)bb * 10 + n];
    }
    __syncthreads();

    // ---- u/v projections: NB*10*32 = 3840 outputs, 15 per thread ----
    #pragma unroll
    for (int q = 0; q < (NB * NN * 32) / THREADS; ++q) {
        int s = tid + q * THREADS;
        int c = s & 31;
        int rest = s >> 5;
        int bl = rest / 10, n = rest - bl * 10;
        float x0 = sIn[bl][n][0], x1 = sIn[bl][n][1], x2 = sIn[bl][n][2];
        float u = sbu[c] + x0 * sWpu[0][c] + x1 * sWpu[1][c] + x2 * sWpu[2][c];
        float v = sbv[c] + x0 * sWpv[0][c] + x1 * sWpv[1][c] + x2 * sWpv[2][c];
        sU[bl][n * UST + c] = u;
        sV[bl][n * UST + c] = v;
    }
    __syncthreads();

    const float4* w2v = (const float4*)sW2;

    // ---- pair phase: 600 duos over 3 rounds (NOT unrolled) ----
    #pragma unroll 1
    for (int r = 0; r < (NDUO + THREADS - 1) / THREADS; ++r) {
        int d = tid + r * THREADS;
        if (d >= NDUO) break;
        int t2 = 2 * d;                 // even pair index within block
        int bl = t2 / 100;
        int p0 = t2 - bl * 100;         // even -> p0, p0+1 share batch and i
        int bb = blockIdx.x * NB + bl;
        if (bb >= B) continue;

        int i   = p0 / 10;
        int jj0 = p0 - i * 10;          // even
        int jj1 = jj0 + 1;              // odd, >= 1
        // idx[i,0] = i ; idx[i,1:] = all j != i ascending
        int j0 = (jj0 == 0) ? i : ((jj0 <= i) ? jj0 - 1 : jj0);
        int j1 = (jj1 <= i) ? jj1 - 1 : jj1;

        // h1a = lrelu(u[i] + v[j0]) ; h1b = lrelu(u[i] + v[j1])
        float h1a[32], h1b[32];
        const float4* uv  = (const float4*)&sU[bl][i  * UST];
        const float4* vv0 = (const float4*)&sV[bl][j0 * UST];
        const float4* vv1 = (const float4*)&sV[bl][j1 * UST];
        #pragma unroll
        for (int q = 0; q < 8; ++q) {
            float4 ua = uv[q];
            float4 va = vv0[q];
            float4 vb = vv1[q];
            h1a[4 * q + 0] = lrelu1(ua.x + va.x);
            h1a[4 * q + 1] = lrelu1(ua.y + va.y);
            h1a[4 * q + 2] = lrelu1(ua.z + va.z);
            h1a[4 * q + 3] = lrelu1(ua.w + va.w);
            h1b[4 * q + 0] = lrelu1(ua.x + vb.x);
            h1b[4 * q + 1] = lrelu1(ua.y + vb.y);
            h1b[4 * q + 2] = lrelu1(ua.z + vb.z);
            h1b[4 * q + 3] = lrelu1(ua.w + vb.w);
        }

        // layer 2 for both pairs, W2 loaded once: 16 independent FMA chains
        float accA[8], accB[8];
        #pragma unroll
        for (int m = 0; m < 8; ++m) { accA[m] = sb2[m]; accB[m] = sb2[m]; }
        #pragma unroll
        for (int c = 0; c < 32; ++c) {
            float4 wa = w2v[2 * c];
            float4 wb = w2v[2 * c + 1];
            float  ha = h1a[c];
            float  hb = h1b[c];
            accA[0] += ha * wa.x; accA[1] += ha * wa.y;
            accA[2] += ha * wa.z; accA[3] += ha * wa.w;
            accA[4] += ha * wb.x; accA[5] += ha * wb.y;
            accA[6] += ha * wb.z; accA[7] += ha * wb.w;
            accB[0] += hb * wa.x; accB[1] += hb * wa.y;
            accB[2] += hb * wa.z; accB[3] += hb * wa.w;
            accB[4] += hb * wb.x; accB[5] += hb * wb.y;
            accB[6] += hb * wb.z; accB[7] += hb * wb.w;
        }

        // layer 3 + argmax for both pairs (W3/b3 broadcast from shared)
        float e0a = sb3[0], e1a = sb3[1];
        float e0b = sb3[0], e1b = sb3[1];
        #pragma unroll
        for (int m = 0; m < 8; ++m) {
            float w0 = sW3[2 * m], w1 = sW3[2 * m + 1];
            float ga = lrelu1(accA[m]);
            float gb = lrelu1(accB[m]);
            e0a += ga * w0; e1a += ga * w1;
            e0b += gb * w0; e1b += gb * w1;
        }

        // fused stores: (bb*100+p0) is even -> float4 edge store is 16B aligned
        size_t eb = (size_t)bb * 100 + p0;
        ((float4*)out_edge)[eb >> 1] = make_float4(e0a, e1a, e0b, e1b);
        if (out_adj) {
            float a0 = (e1a > e0a) ? 1.0f : 0.0f;
            float a1 = (e1b > e0b) ? 1.0f : 0.0f;
            ((float2*)out_adj)[eb >> 1] = make_float2(a0, a1);
        }
    }
}

extern "C" void kernel_launch(void* const* d_in, const int* in_sizes, int n_in,
                              void* d_out, int out_size)
{
    const float* pos = (const float*)d_in[0];
    const float* ori = (const float*)d_in[1];
    const float* Wp  = (const float*)d_in[2];
    const float* bp  = (const float*)d_in[3];
    const float* W1  = (const float*)d_in[4];
    const float* b1  = (const float*)d_in[5];
    const float* W2  = (const float*)d_in[6];
    const float* b2  = (const float*)d_in[7];
    const float* W3  = (const float*)d_in[8];
    const float* b3  = (const float*)d_in[9];

    const int B = in_sizes[0] / 20;   // position is [B,10,2]

    float* out      = (float*)d_out;
    float* out_edge = out;            // B*100*2 floats
    float* out_adj  = ((size_t)out_size >= (size_t)B * 300)
                        ? out + (size_t)B * 200 : (float*)0;

    const int blocks = (B + NB - 1) / NB;
    gpn_kernel<<<blocks, THREADS>>>(pos, ori, Wp, bp, W1, b1, W2, b2, W3, b3,
                                    out_edge, out_adj, B);
}

// round 14
// speedup vs baseline: 2.4581x; 1.0941x over previous
#include <cuda_runtime.h>

// GraphProposalNetwork, scalar fp32, block-cooperative (12 batches/block),
// FIVE pairs (one half-row, shared i) per thread.
//  - feat layer fused into u/v (Wpu=Wp@W1[:16], Wpv=Wp@W1[16:], biases folded)
//  - pair(i,j) layer-1 preact = u[i] + v[j]
//  - layer 2 loops channel-chunks OUTER, pairs INNER: W2 + u loaded once per
//    chunk for 5 pairs -> 22.4 LDS.128/pair (vs 44 in the duo version), only
//    acc[5][8] live (h recomputed in-flight). Summation order per accumulator
//    is unchanged (c ascending) -> bitwise-identical results to R13.

#define NN      10
#define NB      12
#define THREADS 256
#define UST     36   // u/v row stride (floats): 144B, 16B-aligned for LDS.128

__device__ __forceinline__ float lrelu1(float x) {
    return fmaxf(x, 0.2f * x);   // exact for slope 0.2 < 1
}

__global__ __launch_bounds__(THREADS, 2)
void gpn_kernel(const float* __restrict__ pos,   // [B,10,2]
                const float* __restrict__ ori,   // [B,10,1]
                const float* __restrict__ Wp,    // [3,16]
                const float* __restrict__ bp,    // [16]
                const float* __restrict__ W1,    // [32,32]
                const float* __restrict__ b1,    // [32]
                const float* __restrict__ W2,    // [32,8]
                const float* __restrict__ b2,    // [8]
                const float* __restrict__ W3,    // [8,2]
                const float* __restrict__ b3,    // [2]
                float* __restrict__ out_edge,    // [B,10,10,2]
                float* __restrict__ out_adj,     // [B,10,10] (float), may be null
                int B)
{
    __shared__ float sWpu[3][32], sWpv[3][32];
    __shared__ float sbu[32], sbv[32];
    __shared__ __align__(16) float sW2[32 * 8];
    __shared__ float sW3[16], sb2[8], sb3[2];
    __shared__ float sIn[NB][NN][3];
    __shared__ __align__(16) float sU[NB][NN * UST];
    __shared__ __align__(16) float sV[NB][NN * UST];

    const int tid = threadIdx.x;

    // ---- stage fused weights (block-cooperative) ----
    {
        int t = tid;
        if (t < 96) {                       // Wpu[d][c] = sum_k Wp[d][k]*W1[k][c]
            int d = t >> 5, c = t & 31;
            float a = 0.f;
            #pragma unroll
            for (int k = 0; k < 16; ++k) a += Wp[d * 16 + k] * W1[k * 32 + c];
            sWpu[d][c] = a;
        } else if (t < 192) {               // Wpv[d][c] = sum_k Wp[d][k]*W1[16+k][c]
            int tt = t - 96, d = tt >> 5, c = tt & 31;
            float a = 0.f;
            #pragma unroll
            for (int k = 0; k < 16; ++k) a += Wp[d * 16 + k] * W1[(16 + k) * 32 + c];
            sWpv[d][c] = a;
        } else if (t < 224) {               // bu[c] = b1[c] + sum_k bp[k]*W1[k][c]
            int c = t - 192;
            float a = b1[c];
            #pragma unroll
            for (int k = 0; k < 16; ++k) a += bp[k] * W1[k * 32 + c];
            sbu[c] = a;
        } else {                            // bv[c] = sum_k bp[k]*W1[16+k][c]
            int c = t - 224;
            float a = 0.f;
            #pragma unroll
            for (int k = 0; k < 16; ++k) a += bp[k] * W1[(16 + k) * 32 + c];
            sbv[c] = a;
        }
    }
    if (tid < 32 * 8) sW2[tid] = W2[tid];
    if (tid < 16) sW3[tid] = W3[tid];
    if (tid < 8)  sb2[tid] = b2[tid];
    if (tid < 2)  sb3[tid] = b3[tid];

    // ---- stage inputs for NB batches ----
    if (tid < NB * 20) {                    // 240 threads
        int bl = tid / 20, r = tid - bl * 20;
        int bb = blockIdx.x * NB + bl;
        if (bb < B) sIn[bl][r >> 1][r & 1] = pos[(size_t)bb * 20 + r];
    }
    if (tid < NB * 10) {                    // 120 threads
        int bl = tid / 10, n = tid - bl * 10;
        int bb = blockIdx.x * NB + bl;
        if (bb < B) sIn[bl][n][2] = ori[(size_t)bb * 10 + n];
    }
    __syncthreads();

    // ---- u/v projections: NB*10*32 = 3840 outputs, 15 per thread ----
    #pragma unroll
    for (int q = 0; q < (NB * NN * 32) / THREADS; ++q) {
        int s = tid + q * THREADS;
        int c = s & 31;
        int rest = s >> 5;
        int bl = rest / 10, n = rest - bl * 10;
        float x0 = sIn[bl][n][0], x1 = sIn[bl][n][1], x2 = sIn[bl][n][2];
        float u = sbu[c] + x0 * sWpu[0][c] + x1 * sWpu[1][c] + x2 * sWpu[2][c];
        float v = sbv[c] + x0 * sWpv[0][c] + x1 * sWpv[1][c] + x2 * sWpv[2][c];
        sU[bl][n * UST + c] = u;
        sV[bl][n * UST + c] = v;
    }
    __syncthreads();

    // ---- pair phase: one half-row (5 pairs, shared i) per thread ----
    // NB*20 = 240 half-rows, single round.
    if (tid < NB * 20) {
        const int bl   = tid / 20;
        const int rem  = tid - bl * 20;
        const int i    = rem >> 1;
        const int half = rem & 1;
        const int bb   = blockIdx.x * NB + bl;
        if (bb < B) {
            const float4* w2v = (const float4*)sW2;
            const float4* uv  = (const float4*)&sU[bl][i * UST];

            // v row pointers for the 5 jj's of this half
            const float4* vv[5];
            #pragma unroll
            for (int k = 0; k < 5; ++k) {
                int jj = half * 5 + k;
                // idx[i,0] = i ; idx[i,1:] = all j != i ascending
                int j = (jj == 0) ? i : ((jj <= i) ? jj - 1 : jj);
                vv[k] = (const float4*)&sV[bl][j * UST];
            }

            // accumulators (b2 folded in)
            float acc[5][8];
            #pragma unroll
            for (int k = 0; k < 5; ++k)
                #pragma unroll
                for (int m = 0; m < 8; ++m) acc[k][m] = sb2[m];

            // layer 2: chunk loop outer (4 channels/chunk), pairs inner.
            // W2 rows + u loaded once per chunk for all 5 pairs.
            #pragma unroll
            for (int q = 0; q < 8; ++q) {
                float4 u4  = uv[q];
                float4 w0a = w2v[8 * q + 0], w0b = w2v[8 * q + 1];
                float4 w1a = w2v[8 * q + 2], w1b = w2v[8 * q + 3];
                float4 w2a = w2v[8 * q + 4], w2b = w2v[8 * q + 5];
                float4 w3a = w2v[8 * q + 6], w3b = w2v[8 * q + 7];
                #pragma unroll
                for (int k = 0; k < 5; ++k) {
                    float4 v4 = vv[k][q];
                    float h0 = lrelu1(u4.x + v4.x);
                    float h1 = lrelu1(u4.y + v4.y);
                    float h2 = lrelu1(u4.z + v4.z);
                    float h3 = lrelu1(u4.w + v4.w);
                    // c = 4q+0 .. 4q+3, ascending (same order as before)
                    acc[k][0] += h0 * w0a.x; acc[k][1] += h0 * w0a.y;
                    acc[k][2] += h0 * w0a.z; acc[k][3] += h0 * w0a.w;
                    acc[k][4] += h0 * w0b.x; acc[k][5] += h0 * w0b.y;
                    acc[k][6] += h0 * w0b.z; acc[k][7] += h0 * w0b.w;

                    acc[k][0] += h1 * w1a.x; acc[k][1] += h1 * w1a.y;
                    acc[k][2] += h1 * w1a.z; acc[k][3] += h1 * w1a.w;
                    acc[k][4] += h1 * w1b.x; acc[k][5] += h1 * w1b.y;
                    acc[k][6] += h1 * w1b.z; acc[k][7] += h1 * w1b.w;

                    acc[k][0] += h2 * w2a.x; acc[k][1] += h2 * w2a.y;
                    acc[k][2] += h2 * w2a.z; acc[k][3] += h2 * w2a.w;
                    acc[k][4] += h2 * w2b.x; acc[k][5] += h2 * w2b.y;
                    acc[k][6] += h2 * w2b.z; acc[k][7] += h2 * w2b.w;

                    acc[k][0] += h3 * w3a.x; acc[k][1] += h3 * w3a.y;
                    acc[k][2] += h3 * w3a.z; acc[k][3] += h3 * w3a.w;
                    acc[k][4] += h3 * w3b.x; acc[k][5] += h3 * w3b.y;
                    acc[k][6] += h3 * w3b.z; acc[k][7] += h3 * w3b.w;
                }
            }

            // layer 3 + argmax + stores (5 consecutive pairs)
            const size_t eb = (size_t)bb * 100 + 10 * i + 5 * half;
            float2* ep = (float2*)out_edge + eb;
            float*  ap = out_adj ? out_adj + eb : (float*)0;
            #pragma unroll
            for (int k = 0; k < 5; ++k) {
                float e0 = sb3[0], e1 = sb3[1];
                #pragma unroll
                for (int m = 0; m < 8; ++m) {
                    float g = lrelu1(acc[k][m]);
                    e0 += g * sW3[2 * m];
                    e1 += g * sW3[2 * m + 1];
                }
                ep[k] = make_float2(e0, e1);
                if (ap) ap[k] = (e1 > e0) ? 1.0f : 0.0f;
            }
        }
    }
}

extern "C" void kernel_launch(void* const* d_in, const int* in_sizes, int n_in,
                              void* d_out, int out_size)
{
    const float* pos = (const float*)d_in[0];
    const float* ori = (const float*)d_in[1];
    const float* Wp  = (const float*)d_in[2];
    const float* bp  = (const float*)d_in[3];
    const float* W1  = (const float*)d_in[4];
    const float* b1  = (const float*)d_in[5];
    const float* W2  = (const float*)d_in[6];
    const float* b2  = (const float*)d_in[7];
    const float* W3  = (const float*)d_in[8];
    const float* b3  = (const float*)d_in[9];

    const int B = in_sizes[0] / 20;   // position is [B,10,2]

    float* out      = (float*)d_out;
    float* out_edge = out;            // B*100*2 floats
    float* out_adj  = ((size_t)out_size >= (size_t)B * 300)
                        ? out + (size_t)B * 200 : (float*)0;

    const int blocks = (B + NB - 1) / NB;
    gpn_kernel<<<blocks, THREADS>>>(pos, ori, Wp, bp, W1, b1, W2, b2, W3, b3,
                                    out_edge, out_adj, B);
}

// round 15
// speedup vs baseline: 2.4599x; 1.0007x over previous
#include <cuda_runtime.h>

// GraphProposalNetwork, scalar fp32, block-cooperative (8 batches/block),
// FIVE pairs (one half-row, shared i) per thread. 160-thread blocks,
// 4 blocks/SM (20 warps/SM) for latency hiding.
//  - feat layer fused into u/v (Wpu=Wp@W1[:16], Wpv=Wp@W1[16:], biases folded)
//  - pair(i,j) layer-1 preact = u[i] + v[j]
//  - layer 2: channel-chunks OUTER, pairs INNER; W2 + u loaded once per chunk
//    for 5 pairs. Pair body identical to the 43.5us version (bitwise-same).

#define NN      10
#define NB      8
#define THREADS 160
#define UST     36   // u/v row stride (floats): 144B, 16B-aligned for LDS.128

__device__ __forceinline__ float lrelu1(float x) {
    return fmaxf(x, 0.2f * x);   // exact for slope 0.2 < 1
}

__global__ __launch_bounds__(THREADS, 4)
void gpn_kernel(const float* __restrict__ pos,   // [B,10,2]
                const float* __restrict__ ori,   // [B,10,1]
                const float* __restrict__ Wp,    // [3,16]
                const float* __restrict__ bp,    // [16]
                const float* __restrict__ W1,    // [32,32]
                const float* __restrict__ b1,    // [32]
                const float* __restrict__ W2,    // [32,8]
                const float* __restrict__ b2,    // [8]
                const float* __restrict__ W3,    // [8,2]
                const float* __restrict__ b3,    // [2]
                float* __restrict__ out_edge,    // [B,10,10,2]
                float* __restrict__ out_adj,     // [B,10,10] (float), may be null
                int B)
{
    __shared__ float sWpu[3][32], sWpv[3][32];
    __shared__ float sbu[32], sbv[32];
    __shared__ __align__(16) float sW2[32 * 8];
    __shared__ float sW3[16], sb2[8], sb3[2];
    __shared__ float sIn[NB][NN][3];
    __shared__ __align__(16) float sU[NB][NN * UST];
    __shared__ __align__(16) float sV[NB][NN * UST];

    const int tid = threadIdx.x;

    // ---- stage fused weights: strided so 160 threads cover 256 slots ----
    for (int s = tid; s < 256; s += THREADS) {
        if (s < 96) {                       // Wpu[d][c] = sum_k Wp[d][k]*W1[k][c]
            int d = s >> 5, c = s & 31;
            float a = 0.f;
            #pragma unroll
            for (int k = 0; k < 16; ++k) a += Wp[d * 16 + k] * W1[k * 32 + c];
            sWpu[d][c] = a;
        } else if (s < 192) {               // Wpv[d][c] = sum_k Wp[d][k]*W1[16+k][c]
            int ss = s - 96, d = ss >> 5, c = ss & 31;
            float a = 0.f;
            #pragma unroll
            for (int k = 0; k < 16; ++k) a += Wp[d * 16 + k] * W1[(16 + k) * 32 + c];
            sWpv[d][c] = a;
        } else if (s < 224) {               // bu[c] = b1[c] + sum_k bp[k]*W1[k][c]
            int c = s - 192;
            float a = b1[c];
            #pragma unroll
            for (int k = 0; k < 16; ++k) a += bp[k] * W1[k * 32 + c];
            sbu[c] = a;
        } else {                            // bv[c] = sum_k bp[k]*W1[16+k][c]
            int c = s - 224;
            float a = 0.f;
            #pragma unroll
            for (int k = 0; k < 16; ++k) a += bp[k] * W1[(16 + k) * 32 + c];
            sbv[c] = a;
        }
    }
    for (int s = tid; s < 32 * 8; s += THREADS) sW2[s] = W2[s];
    if (tid < 16) sW3[tid] = W3[tid];
    if (tid < 8)  sb2[tid] = b2[tid];
    if (tid < 2)  sb3[tid] = b3[tid];

    // ---- stage inputs for NB batches ----
    {                                       // NB*20 = 160 = THREADS exactly
        int bl = tid / 20, r = tid - bl * 20;
        int bb = blockIdx.x * NB + bl;
        if (bb < B) sIn[bl][r >> 1][r & 1] = pos[(size_t)bb * 20 + r];
    }
    if (tid < NB * 10) {                    // 80 threads
        int bl = tid / 10, n = tid - bl * 10;
        int bb = blockIdx.x * NB + bl;
        if (bb < B) sIn[bl][n][2] = ori[(size_t)bb * 10 + n];
    }
    __syncthreads();

    // ---- u/v projections: NB*10*32 = 2560 outputs, 16 per thread ----
    #pragma unroll
    for (int q = 0; q < (NB * NN * 32) / THREADS; ++q) {
        int s = tid + q * THREADS;
        int c = s & 31;
        int rest = s >> 5;
        int bl = rest / 10, n = rest - bl * 10;
        float x0 = sIn[bl][n][0], x1 = sIn[bl][n][1], x2 = sIn[bl][n][2];
        float u = sbu[c] + x0 * sWpu[0][c] + x1 * sWpu[1][c] + x2 * sWpu[2][c];
        float v = sbv[c] + x0 * sWpv[0][c] + x1 * sWpv[1][c] + x2 * sWpv[2][c];
        sU[bl][n * UST + c] = u;
        sV[bl][n * UST + c] = v;
    }
    __syncthreads();

    // ---- pair phase: one half-row (5 pairs, shared i) per thread ----
    // NB*20 = 160 half-rows = THREADS, single round, all lanes active.
    {
        const int bl   = tid / 20;
        const int rem  = tid - bl * 20;
        const int i    = rem >> 1;
        const int half = rem & 1;
        const int bb   = blockIdx.x * NB + bl;
        if (bb < B) {
            const float4* w2v = (const float4*)sW2;
            const float4* uv  = (const float4*)&sU[bl][i * UST];

            // v row pointers for the 5 jj's of this half
            const float4* vv[5];
            #pragma unroll
            for (int k = 0; k < 5; ++k) {
                int jj = half * 5 + k;
                // idx[i,0] = i ; idx[i,1:] = all j != i ascending
                int j = (jj == 0) ? i : ((jj <= i) ? jj - 1 : jj);
                vv[k] = (const float4*)&sV[bl][j * UST];
            }

            // accumulators (b2 folded in)
            float acc[5][8];
            #pragma unroll
            for (int k = 0; k < 5; ++k)
                #pragma unroll
                for (int m = 0; m < 8; ++m) acc[k][m] = sb2[m];

            // layer 2: chunk loop outer (4 channels/chunk), pairs inner.
            #pragma unroll
            for (int q = 0; q < 8; ++q) {
                float4 u4  = uv[q];
                float4 w0a = w2v[8 * q + 0], w0b = w2v[8 * q + 1];
                float4 w1a = w2v[8 * q + 2], w1b = w2v[8 * q + 3];
                float4 w2a = w2v[8 * q + 4], w2b = w2v[8 * q + 5];
                float4 w3a = w2v[8 * q + 6], w3b = w2v[8 * q + 7];
                #pragma unroll
                for (int k = 0; k < 5; ++k) {
                    float4 v4 = vv[k][q];
                    float h0 = lrelu1(u4.x + v4.x);
                    float h1 = lrelu1(u4.y + v4.y);
                    float h2 = lrelu1(u4.z + v4.z);
                    float h3 = lrelu1(u4.w + v4.w);
                    acc[k][0] += h0 * w0a.x; acc[k][1] += h0 * w0a.y;
                    acc[k][2] += h0 * w0a.z; acc[k][3] += h0 * w0a.w;
                    acc[k][4] += h0 * w0b.x; acc[k][5] += h0 * w0b.y;
                    acc[k][6] += h0 * w0b.z; acc[k][7] += h0 * w0b.w;

                    acc[k][0] += h1 * w1a.x; acc[k][1] += h1 * w1a.y;
                    acc[k][2] += h1 * w1a.z; acc[k][3] += h1 * w1a.w;
                    acc[k][4] += h1 * w1b.x; acc[k][5] += h1 * w1b.y;
                    acc[k][6] += h1 * w1b.z; acc[k][7] += h1 * w1b.w;

                    acc[k][0] += h2 * w2a.x; acc[k][1] += h2 * w2a.y;
                    acc[k][2] += h2 * w2a.z; acc[k][3] += h2 * w2a.w;
                    acc[k][4] += h2 * w2b.x; acc[k][5] += h2 * w2b.y;
                    acc[k][6] += h2 * w2b.z; acc[k][7] += h2 * w2b.w;

                    acc[k][0] += h3 * w3a.x; acc[k][1] += h3 * w3a.y;
                    acc[k][2] += h3 * w3a.z; acc[k][3] += h3 * w3a.w;
                    acc[k][4] += h3 * w3b.x; acc[k][5] += h3 * w3b.y;
                    acc[k][6] += h3 * w3b.z; acc[k][7] += h3 * w3b.w;
                }
            }

            // layer 3 + argmax + stores (5 consecutive pairs)
            const size_t eb = (size_t)bb * 100 + 10 * i + 5 * half;
            float2* ep = (float2*)out_edge + eb;
            float*  ap = out_adj ? out_adj + eb : (float*)0;
            #pragma unroll
            for (int k = 0; k < 5; ++k) {
                float e0 = sb3[0], e1 = sb3[1];
                #pragma unroll
                for (int m = 0; m < 8; ++m) {
                    float g = lrelu1(acc[k][m]);
                    e0 += g * sW3[2 * m];
                    e1 += g * sW3[2 * m + 1];
                }
                ep[k] = make_float2(e0, e1);
                if (ap) ap[k] = (e1 > e0) ? 1.0f : 0.0f;
            }
        }
    }
}

extern "C" void kernel_launch(void* const* d_in, const int* in_sizes, int n_in,
                              void* d_out, int out_size)
{
    const float* pos = (const float*)d_in[0];
    const float* ori = (const float*)d_in[1];
    const float* Wp  = (const float*)d_in[2];
    const float* bp  = (const float*)d_in[3];
    const float* W1  = (const float*)d_in[4];
    const float* b1  = (const float*)d_in[5];
    const float* W2  = (const float*)d_in[6];
    const float* b2  = (const float*)d_in[7];
    const float* W3  = (const float*)d_in[8];
    const float* b3  = (const float*)d_in[9];

    const int B = in_sizes[0] / 20;   // position is [B,10,2]

    float* out      = (float*)d_out;
    float* out_edge = out;            // B*100*2 floats
    float* out_adj  = ((size_t)out_size >= (size_t)B * 300)
                        ? out + (size_t)B * 200 : (float*)0;

    const int blocks = (B + NB - 1) / NB;
    gpn_kernel<<<blocks, THREADS>>>(pos, ori, Wp, bp, W1, b1, W2, b2, W3, b3,
                                    out_edge, out_adj, B);
}

// round 17
// speedup vs baseline: 3.0281x; 1.2310x over previous
#include <cuda_runtime.h>

// GraphProposalNetwork, fp32, block-cooperative (8 batches/block),
// FIVE pairs (one half-row, shared i) per thread, 160-thread blocks.
// This round: layer-2 inner block converted to packed fma.rn.f32x2 (FFMA2):
//   accumulators packed over adjacent output channels (acc2[5][4] u64),
//   W2 read from the SAME natural shared layout as ulonglong2,
//   h duplicated via one mov.b64 {h,h}. Per-accumulator summation order is
//   unchanged -> bitwise-identical results to the 43.5us scalar version.

#define NN      10
#define NB      8
#define THREADS 160
#define UST     36   // u/v row stride (floats): 144B, 16B-aligned for LDS.128

typedef unsigned long long ull;

__device__ __forceinline__ float lrelu1(float x) {
    return fmaxf(x, 0.2f * x);   // exact for slope 0.2 < 1
}
__device__ __forceinline__ ull pack_dup(float x) {
    ull d; asm("mov.b64 %0, {%1, %1};" : "=l"(d) : "f"(x)); return d;
}
__device__ __forceinline__ ull f2_fma(ull a, ull b, ull c) {
    ull d; asm("fma.rn.f32x2 %0, %1, %2, %3;" : "=l"(d) : "l"(a), "l"(b), "l"(c)); return d;
}
__device__ __forceinline__ float2 unpack2(ull x) {
    float lo, hi;
    asm("mov.b64 {%0, %1}, %2;" : "=f"(lo), "=f"(hi) : "l"(x));
    return make_float2(lo, hi);
}

__global__ __launch_bounds__(THREADS, 4)
void gpn_kernel(const float* __restrict__ pos,   // [B,10,2]
                const float* __restrict__ ori,   // [B,10,1]
                const float* __restrict__ Wp,    // [3,16]
                const float* __restrict__ bp,    // [16]
                const float* __restrict__ W1,    // [32,32]
                const float* __restrict__ b1,    // [32]
                const float* __restrict__ W2,    // [32,8]
                const float* __restrict__ b2,    // [8]
                const float* __restrict__ W3,    // [8,2]
                const float* __restrict__ b3,    // [2]
                float* __restrict__ out_edge,    // [B,10,10,2]
                float* __restrict__ out_adj,     // [B,10,10] (float), may be null
                int B)
{
    __shared__ float sWpu[3][32], sWpv[3][32];
    __shared__ float sbu[32], sbv[32];
    __shared__ __align__(16) float sW2[32 * 8];   // natural [c][m] layout
    __shared__ float sW3[16], sb2[8], sb3[2];
    __shared__ float sIn[NB][NN][3];
    __shared__ __align__(16) float sU[NB][NN * UST];
    __shared__ __align__(16) float sV[NB][NN * UST];

    const int tid = threadIdx.x;

    // ---- stage fused weights: strided so 160 threads cover 256 slots ----
    for (int s = tid; s < 256; s += THREADS) {
        if (s < 96) {                       // Wpu[d][c] = sum_k Wp[d][k]*W1[k][c]
            int d = s >> 5, c = s & 31;
            float a = 0.f;
            #pragma unroll
            for (int k = 0; k < 16; ++k) a += Wp[d * 16 + k] * W1[k * 32 + c];
            sWpu[d][c] = a;
        } else if (s < 192) {               // Wpv[d][c] = sum_k Wp[d][k]*W1[16+k][c]
            int ss = s - 96, d = ss >> 5, c = ss & 31;
            float a = 0.f;
            #pragma unroll
            for (int k = 0; k < 16; ++k) a += Wp[d * 16 + k] * W1[(16 + k) * 32 + c];
            sWpv[d][c] = a;
        } else if (s < 224) {               // bu[c] = b1[c] + sum_k bp[k]*W1[k][c]
            int c = s - 192;
            float a = b1[c];
            #pragma unroll
            for (int k = 0; k < 16; ++k) a += bp[k] * W1[k * 32 + c];
            sbu[c] = a;
        } else {                            // bv[c] = sum_k bp[k]*W1[16+k][c]
            int c = s - 224;
            float a = 0.f;
            #pragma unroll
            for (int k = 0; k < 16; ++k) a += bp[k] * W1[(16 + k) * 32 + c];
            sbv[c] = a;
        }
    }
    for (int s = tid; s < 32 * 8; s += THREADS) sW2[s] = W2[s];
    if (tid < 16) sW3[tid] = W3[tid];
    if (tid < 8)  sb2[tid] = b2[tid];
    if (tid < 2)  sb3[tid] = b3[tid];

    // ---- stage inputs for NB batches ----
    {                                       // NB*20 = 160 = THREADS exactly
        int bl = tid / 20, r = tid - bl * 20;
        int bb = blockIdx.x * NB + bl;
        if (bb < B) sIn[bl][r >> 1][r & 1] = pos[(size_t)bb * 20 + r];
    }
    if (tid < NB * 10) {                    // 80 threads
        int bl = tid / 10, n = tid - bl * 10;
        int bb = blockIdx.x * NB + bl;
        if (bb < B) sIn[bl][n][2] = ori[(size_t)bb * 10 + n];
    }
    __syncthreads();

    // ---- u/v projections: NB*10*32 = 2560 outputs, 16 per thread ----
    #pragma unroll
    for (int q = 0; q < (NB * NN * 32) / THREADS; ++q) {
        int s = tid + q * THREADS;
        int c = s & 31;
        int rest = s >> 5;
        int bl = rest / 10, n = rest - bl * 10;
        float x0 = sIn[bl][n][0], x1 = sIn[bl][n][1], x2 = sIn[bl][n][2];
        float u = sbu[c] + x0 * sWpu[0][c] + x1 * sWpu[1][c] + x2 * sWpu[2][c];
        float v = sbv[c] + x0 * sWpv[0][c] + x1 * sWpv[1][c] + x2 * sWpv[2][c];
        sU[bl][n * UST + c] = u;
        sV[bl][n * UST + c] = v;
    }
    __syncthreads();

    // ---- pair phase: one half-row (5 pairs, shared i) per thread ----
    {
        const int bl   = tid / 20;
        const int rem  = tid - bl * 20;
        const int i    = rem >> 1;
        const int half = rem & 1;
        const int bb   = blockIdx.x * NB + bl;
        if (bb < B) {
            // W2 row c as two packed-pair vectors:
            //   w2p[2c]   = ((m0,m1),(m2,m3)), w2p[2c+1] = ((m4,m5),(m6,m7))
            const ulonglong2* w2p = (const ulonglong2*)sW2;
            const float4*     uv  = (const float4*)&sU[bl][i * UST];

            // v row pointers for the 5 jj's of this half
            const float4* vv[5];
            #pragma unroll
            for (int k = 0; k < 5; ++k) {
                int jj = half * 5 + k;
                // idx[i,0] = i ; idx[i,1:] = all j != i ascending
                int j = (jj == 0) ? i : ((jj <= i) ? jj - 1 : jj);
                vv[k] = (const float4*)&sV[bl][j * UST];
            }

            // packed accumulators: acc2[k][m2] = (acc[2m2], acc[2m2+1]), b2 folded
            ull acc2[5][4];
            {
                ull i0 = ((const ull*)sb2)[0], i1 = ((const ull*)sb2)[1];
                ull i2 = ((const ull*)sb2)[2], i3 = ((const ull*)sb2)[3];
                #pragma unroll
                for (int k = 0; k < 5; ++k) {
                    acc2[k][0] = i0; acc2[k][1] = i1;
                    acc2[k][2] = i2; acc2[k][3] = i3;
                }
            }

            // layer 2: chunk loop outer (4 channels/chunk), pairs inner.
            // Per channel: h duplicated once, 4 FFMA2 replace 8 FFMA.
            #pragma unroll
            for (int q = 0; q < 8; ++q) {
                float4 u4 = uv[q];
                ulonglong2 W0 = w2p[2 * (4 * q + 0)], W0b = w2p[2 * (4 * q + 0) + 1];
                ulonglong2 W1r = w2p[2 * (4 * q + 1)], W1b = w2p[2 * (4 * q + 1) + 1];
                ulonglong2 W2r = w2p[2 * (4 * q + 2)], W2b = w2p[2 * (4 * q + 2) + 1];
                ulonglong2 W3r = w2p[2 * (4 * q + 3)], W3b = w2p[2 * (4 * q + 3) + 1];
                #pragma unroll
                for (int k = 0; k < 5; ++k) {
                    float4 v4 = vv[k][q];
                    ull h0 = pack_dup(lrelu1(u4.x + v4.x));
                    ull h1 = pack_dup(lrelu1(u4.y + v4.y));
                    ull h2 = pack_dup(lrelu1(u4.z + v4.z));
                    ull h3 = pack_dup(lrelu1(u4.w + v4.w));
                    // c ascending, m-within-pack ascending: same per-acc order
                    acc2[k][0] = f2_fma(h0, W0.x,  acc2[k][0]);
                    acc2[k][1] = f2_fma(h0, W0.y,  acc2[k][1]);
                    acc2[k][2] = f2_fma(h0, W0b.x, acc2[k][2]);
                    acc2[k][3] = f2_fma(h0, W0b.y, acc2[k][3]);

                    acc2[k][0] = f2_fma(h1, W1r.x, acc2[k][0]);
                    acc2[k][1] = f2_fma(h1, W1r.y, acc2[k][1]);
                    acc2[k][2] = f2_fma(h1, W1b.x, acc2[k][2]);
                    acc2[k][3] = f2_fma(h1, W1b.y, acc2[k][3]);

                    acc2[k][0] = f2_fma(h2, W2r.x, acc2[k][0]);
                    acc2[k][1] = f2_fma(h2, W2r.y, acc2[k][1]);
                    acc2[k][2] = f2_fma(h2, W2b.x, acc2[k][2]);
                    acc2[k][3] = f2_fma(h2, W2b.y, acc2[k][3]);

                    acc2[k][0] = f2_fma(h3, W3r.x, acc2[k][0]);
                    acc2[k][1] = f2_fma(h3, W3r.y, acc2[k][1]);
                    acc2[k][2] = f2_fma(h3, W3b.x, acc2[k][2]);
                    acc2[k][3] = f2_fma(h3, W3b.y, acc2[k][3]);
                }
            }

            // layer 3 + argmax + stores (5 consecutive pairs), scalar
            const size_t eb = (size_t)bb * 100 + 10 * i + 5 * half;
            float2* ep = (float2*)out_edge + eb;
            float*  ap = out_adj ? out_adj + eb : (float*)0;
            #pragma unroll
            for (int k = 0; k < 5; ++k) {
                float e0 = sb3[0], e1 = sb3[1];
                #pragma unroll
                for (int m2 = 0; m2 < 4; ++m2) {
                    float2 a2 = unpack2(acc2[k][m2]);
                    float g0 = lrelu1(a2.x);
                    float g1 = lrelu1(a2.y);
                    e0 += g0 * sW3[4 * m2 + 0];
                    e1 += g0 * sW3[4 * m2 + 1];
                    e0 += g1 * sW3[4 * m2 + 2];
                    e1 += g1 * sW3[4 * m2 + 3];
                }
                ep[k] = make_float2(e0, e1);
                if (ap) ap[k] = (e1 > e0) ? 1.0f : 0.0f;
            }
        }
    }
}

extern "C" void kernel_launch(void* const* d_in, const int* in_sizes, int n_in,
                              void* d_out, int out_size)
{
    const float* pos = (const float*)d_in[0];
    const float* ori = (const float*)d_in[1];
    const float* Wp  = (const float*)d_in[2];
    const float* bp  = (const float*)d_in[3];
    const float* W1  = (const float*)d_in[4];
    const float* b1  = (const float*)d_in[5];
    const float* W2  = (const float*)d_in[6];
    const float* b2  = (const float*)d_in[7];
    const float* W3  = (const float*)d_in[8];
    const float* b3  = (const float*)d_in[9];

    const int B = in_sizes[0] / 20;   // position is [B,10,2]

    float* out      = (float*)d_out;
    float* out_edge = out;            // B*100*2 floats
    float* out_adj  = ((size_t)out_size >= (size_t)B * 300)
                        ? out + (size_t)B * 200 : (float*)0;

    const int blocks = (B + NB - 1) / NB;
    gpn_kernel<<<blocks, THREADS>>>(pos, ori, Wp, bp, W1, b1, W2, b2, W3, b3,
                                    out_edge, out_adj, B);
}